// round 1
// baseline (speedup 1.0000x reference)
#include <cuda_runtime.h>
#include <math.h>

#define Bsz 64
#define Lsz 128
#define Tsz 48
#define Esz 512
#define HEsz 1024
#define Hsz 1024

// ---------------- scratch (device globals; no allocation allowed) ----------------
__device__ float g_h1[2][Bsz * Hsz];
__device__ float g_h2[2][Bsz * Hsz];
__device__ float g_c1[Bsz * Hsz];
__device__ float g_c2[Bsz * Hsz];
__device__ float g_o[Bsz * Hsz];
__device__ float g_q[Bsz * HEsz];
__device__ float g_at[Bsz * HEsz];

__device__ __forceinline__ float sigmoidf_(float x) { return 1.f / (1.f + expf(-x)); }

// =====================================================================
// Fused LSTM cell kernel: gates = sum_seg x_seg @ W_seg^T  (+ biases),
// then pointwise LSTM update. CTA handles 8 h-columns (x4 gates) for all 64 b.
// Thread layout: tn = tid&7 -> one h (4 gates via float4 of Ws),
//                tb = tid>>3 -> 4 b's. acc[4 b][4 gates].
// =====================================================================
template <int NSEG>
__global__ void __launch_bounds__(128) lstm_kernel(
    const float* __restrict__ x0, const float* __restrict__ w0, int K0, int ld0,
    const float* __restrict__ x1, const float* __restrict__ w1, int K1, int ld1,
    const float* __restrict__ x2, const float* __restrict__ w2, int K2, int ld2,
    const float* __restrict__ b_ih, const float* __restrict__ b_hh,
    float* __restrict__ h_out, float* __restrict__ c_io)
{
    __shared__ float Xs[32][68];  // [k][b], padded
    __shared__ float Ws[32][36];  // [k][n], n = h_local*4 + gate, padded

    const int tid = threadIdx.x;
    const int tn = tid & 7;    // h within tile
    const int tb = tid >> 3;   // b group (16 groups of 4)
    const int h0 = blockIdx.x * 8;

    float acc[4][4];
#pragma unroll
    for (int j = 0; j < 4; j++)
#pragma unroll
        for (int i = 0; i < 4; i++) acc[j][i] = 0.f;

#pragma unroll
    for (int seg = 0; seg < NSEG; ++seg) {
        const float* x = (seg == 0) ? x0 : (seg == 1 ? x1 : x2);
        const float* w = (seg == 0) ? w0 : (seg == 1 ? w1 : w2);
        const int Ks  = (seg == 0) ? K0 : (seg == 1 ? K1 : K2);
        const int ldw = (seg == 0) ? ld0 : (seg == 1 ? ld1 : ld2);

        for (int k0 = 0; k0 < Ks; k0 += 32) {
            __syncthreads();
            // load X tile (64 b x 32 k), k-major in smem
#pragma unroll
            for (int i = 0; i < 4; i++) {
                int idx = tid + i * 128;       // 0..511
                int b = idx >> 3, k4 = idx & 7;
                float4 v = *reinterpret_cast<const float4*>(x + b * Ks + k0 + k4 * 4);
                Xs[k4 * 4 + 0][b] = v.x;
                Xs[k4 * 4 + 1][b] = v.y;
                Xs[k4 * 4 + 2][b] = v.z;
                Xs[k4 * 4 + 3][b] = v.w;
            }
            // load W tile: 32 rows (8 h x 4 gates) x 32 k
#pragma unroll
            for (int i = 0; i < 2; i++) {
                int idx = tid + i * 128;       // 0..255
                int n = idx >> 3, k4 = idx & 7;
                int gate = n & 3, hl = n >> 2;
                const float* wr = w + (size_t)(gate * Hsz + h0 + hl) * ldw + k0 + k4 * 4;
                float4 v = *reinterpret_cast<const float4*>(wr);
                Ws[k4 * 4 + 0][n] = v.x;
                Ws[k4 * 4 + 1][n] = v.y;
                Ws[k4 * 4 + 2][n] = v.z;
                Ws[k4 * 4 + 3][n] = v.w;
            }
            __syncthreads();
#pragma unroll
            for (int kk = 0; kk < 32; kk++) {
                float4 xv = *reinterpret_cast<const float4*>(&Xs[kk][tb * 4]);
                float4 wv = *reinterpret_cast<const float4*>(&Ws[kk][tn * 4]);
                acc[0][0] += xv.x * wv.x; acc[0][1] += xv.x * wv.y;
                acc[0][2] += xv.x * wv.z; acc[0][3] += xv.x * wv.w;
                acc[1][0] += xv.y * wv.x; acc[1][1] += xv.y * wv.y;
                acc[1][2] += xv.y * wv.z; acc[1][3] += xv.y * wv.w;
                acc[2][0] += xv.z * wv.x; acc[2][1] += xv.z * wv.y;
                acc[2][2] += xv.z * wv.z; acc[2][3] += xv.z * wv.w;
                acc[3][0] += xv.w * wv.x; acc[3][1] += xv.w * wv.y;
                acc[3][2] += xv.w * wv.z; acc[3][3] += xv.w * wv.w;
            }
        }
    }

    // pointwise LSTM update
    const int h = h0 + tn;
    const float bi = b_ih[h] + b_hh[h];
    const float bf = b_ih[Hsz + h] + b_hh[Hsz + h];
    const float bg = b_ih[2 * Hsz + h] + b_hh[2 * Hsz + h];
    const float bo = b_ih[3 * Hsz + h] + b_hh[3 * Hsz + h];
#pragma unroll
    for (int j = 0; j < 4; j++) {
        int b = tb * 4 + j;
        float ig = sigmoidf_(acc[j][0] + bi);
        float fg = sigmoidf_(acc[j][1] + bf);
        float gg = tanhf(acc[j][2] + bg);
        float og = sigmoidf_(acc[j][3] + bo);
        float c = c_io[b * Hsz + h];
        float cn = fg * c + ig * gg;
        c_io[b * Hsz + h] = cn;
        h_out[b * Hsz + h] = og * tanhf(cn);
    }
}

// =====================================================================
// q = h2 @ W_att   (W_att is (H, HE) row-major, i.e. k-major for this GEMM)
// output (64, 1024). Tile 64 x 16. K = 1024.
// =====================================================================
__global__ void __launch_bounds__(128) q_kernel(
    const float* __restrict__ h2, const float* __restrict__ W, float* __restrict__ qout)
{
    __shared__ float Xs[32][68];
    __shared__ float Ws[32][20];  // [k][n], n-tile 16, padded

    const int tid = threadIdx.x;
    const int tn = tid & 3;    // 4 n-groups of 4
    const int tb = tid >> 2;   // 32 b-groups of 2
    const int n0 = blockIdx.x * 16;

    float acc[2][4];
#pragma unroll
    for (int j = 0; j < 2; j++)
#pragma unroll
        for (int i = 0; i < 4; i++) acc[j][i] = 0.f;

    for (int k0 = 0; k0 < Hsz; k0 += 32) {
        __syncthreads();
#pragma unroll
        for (int i = 0; i < 4; i++) {
            int idx = tid + i * 128;
            int b = idx >> 3, k4 = idx & 7;
            float4 v = *reinterpret_cast<const float4*>(h2 + b * Hsz + k0 + k4 * 4);
            Xs[k4 * 4 + 0][b] = v.x;
            Xs[k4 * 4 + 1][b] = v.y;
            Xs[k4 * 4 + 2][b] = v.z;
            Xs[k4 * 4 + 3][b] = v.w;
        }
        {
            int kk = tid >> 2;       // 0..31
            int n4 = tid & 3;        // 0..3 (4 floats each)
            float4 v = *reinterpret_cast<const float4*>(W + (size_t)(k0 + kk) * HEsz + n0 + n4 * 4);
            Ws[kk][n4 * 4 + 0] = v.x;
            Ws[kk][n4 * 4 + 1] = v.y;
            Ws[kk][n4 * 4 + 2] = v.z;
            Ws[kk][n4 * 4 + 3] = v.w;
        }
        __syncthreads();
#pragma unroll
        for (int kk = 0; kk < 32; kk++) {
            float2 xv = *reinterpret_cast<const float2*>(&Xs[kk][tb * 2]);
            float4 wv = *reinterpret_cast<const float4*>(&Ws[kk][tn * 4]);
            acc[0][0] += xv.x * wv.x; acc[0][1] += xv.x * wv.y;
            acc[0][2] += xv.x * wv.z; acc[0][3] += xv.x * wv.w;
            acc[1][0] += xv.y * wv.x; acc[1][1] += xv.y * wv.y;
            acc[1][2] += xv.y * wv.z; acc[1][3] += xv.y * wv.w;
        }
    }
#pragma unroll
    for (int j = 0; j < 2; j++) {
        int b = tb * 2 + j;
#pragma unroll
        for (int i = 0; i < 4; i++) {
            qout[b * HEsz + n0 + tn * 4 + i] = acc[j][i];
        }
    }
}

// =====================================================================
// Attention: e[b,l] = q[b] . enc[b,l]; masked softmax over l; a_t[b] = sum alpha*enc[b,l]
// One CTA per b. (b_att dropped: softmax is shift-invariant per row.)
// =====================================================================
__global__ void __launch_bounds__(256) att_kernel(
    const float* __restrict__ q, const float* __restrict__ enc,
    const int* __restrict__ masks, float* __restrict__ a_t)
{
    const int b = blockIdx.x;
    const int tid = threadIdx.x, lane = tid & 31, warp = tid >> 5;
    __shared__ float qs[HEsz];
    __shared__ float e[Lsz];

#pragma unroll
    for (int i = 0; i < 4; i++) qs[tid + 256 * i] = q[b * HEsz + tid + 256 * i];
    __syncthreads();

    const float* encb = enc + (size_t)b * Lsz * HEsz;
    for (int i = 0; i < 16; i++) {
        int l = warp * 16 + i;
        const float* er = encb + l * HEsz;
        float s = 0.f;
#pragma unroll 8
        for (int k = lane; k < HEsz; k += 32) s += qs[k] * er[k];
#pragma unroll
        for (int off = 16; off; off >>= 1) s += __shfl_xor_sync(0xffffffffu, s, off);
        if (lane == 0) e[l] = s;
    }
    __syncthreads();

    if (warp == 0) {
        float v[4];
        float m = -INFINITY;
#pragma unroll
        for (int i = 0; i < 4; i++) {
            int l = lane + 32 * i;
            v[i] = (masks[b * Lsz + l] != 0) ? -INFINITY : e[l];
            m = fmaxf(m, v[i]);
        }
#pragma unroll
        for (int off = 16; off; off >>= 1) m = fmaxf(m, __shfl_xor_sync(0xffffffffu, m, off));
        float s = 0.f;
#pragma unroll
        for (int i = 0; i < 4; i++) { v[i] = expf(v[i] - m); s += v[i]; }
#pragma unroll
        for (int off = 16; off; off >>= 1) s += __shfl_xor_sync(0xffffffffu, s, off);
        float inv = 1.f / s;
#pragma unroll
        for (int i = 0; i < 4; i++) e[lane + 32 * i] = v[i] * inv;
    }
    __syncthreads();

    float s0 = 0.f, s1 = 0.f, s2 = 0.f, s3 = 0.f;
#pragma unroll 4
    for (int l = 0; l < Lsz; l++) {
        float al = e[l];
        const float* er = encb + l * HEsz;
        s0 += al * er[tid];
        s1 += al * er[tid + 256];
        s2 += al * er[tid + 512];
        s3 += al * er[tid + 768];
    }
    a_t[b * HEsz + tid] = s0;
    a_t[b * HEsz + tid + 256] = s1;
    a_t[b * HEsz + tid + 512] = s2;
    a_t[b * HEsz + tid + 768] = s3;
}

// =====================================================================
// o_t = tanh([a_t, h2] @ W_comb^T + b_comb). Tile 64 x 16, 2 segments K=1024 each.
// Writes g_o and d_out slice.
// =====================================================================
__global__ void __launch_bounds__(128) comb_kernel(
    const float* __restrict__ x0, const float* __restrict__ w0,
    const float* __restrict__ x1, const float* __restrict__ w1,
    const float* __restrict__ bias,
    float* __restrict__ o_out, float* __restrict__ dout)
{
    __shared__ float Xs[32][68];
    __shared__ float Ws[32][20];

    const int tid = threadIdx.x;
    const int tn = tid & 3;
    const int tb = tid >> 2;
    const int n0 = blockIdx.x * 16;
    const int ldw = 2 * Hsz;

    float acc[2][4];
#pragma unroll
    for (int j = 0; j < 2; j++)
#pragma unroll
        for (int i = 0; i < 4; i++) acc[j][i] = 0.f;

#pragma unroll
    for (int seg = 0; seg < 2; ++seg) {
        const float* x = seg ? x1 : x0;
        const float* w = seg ? w1 : w0;
        for (int k0 = 0; k0 < Hsz; k0 += 32) {
            __syncthreads();
#pragma unroll
            for (int i = 0; i < 4; i++) {
                int idx = tid + i * 128;
                int b = idx >> 3, k4 = idx & 7;
                float4 v = *reinterpret_cast<const float4*>(x + b * Hsz + k0 + k4 * 4);
                Xs[k4 * 4 + 0][b] = v.x;
                Xs[k4 * 4 + 1][b] = v.y;
                Xs[k4 * 4 + 2][b] = v.z;
                Xs[k4 * 4 + 3][b] = v.w;
            }
            {
                int n = tid >> 3;      // 0..15
                int k4 = tid & 7;      // 0..7
                const float* wr = w + (size_t)(n0 + n) * ldw + k0 + k4 * 4;
                float4 v = *reinterpret_cast<const float4*>(wr);
                Ws[k4 * 4 + 0][n] = v.x;
                Ws[k4 * 4 + 1][n] = v.y;
                Ws[k4 * 4 + 2][n] = v.z;
                Ws[k4 * 4 + 3][n] = v.w;
            }
            __syncthreads();
#pragma unroll
            for (int kk = 0; kk < 32; kk++) {
                float2 xv = *reinterpret_cast<const float2*>(&Xs[kk][tb * 2]);
                float4 wv = *reinterpret_cast<const float4*>(&Ws[kk][tn * 4]);
                acc[0][0] += xv.x * wv.x; acc[0][1] += xv.x * wv.y;
                acc[0][2] += xv.x * wv.z; acc[0][3] += xv.x * wv.w;
                acc[1][0] += xv.y * wv.x; acc[1][1] += xv.y * wv.y;
                acc[1][2] += xv.y * wv.z; acc[1][3] += xv.y * wv.w;
            }
        }
    }
#pragma unroll
    for (int j = 0; j < 2; j++) {
        int b = tb * 2 + j;
#pragma unroll
        for (int i = 0; i < 4; i++) {
            int n = n0 + tn * 4 + i;
            float v = tanhf(acc[j][i] + bias[n]);
            o_out[b * Hsz + n] = v;
            dout[b * Hsz + n] = v;
        }
    }
}

// =====================================================================
extern "C" void kernel_launch(void* const* d_in, const int* in_sizes, int n_in,
                              void* d_out, int out_size)
{
    const float* enc      = (const float*)d_in[0];
    const int*   masks    = (const int*)d_in[1];
    const float* h1i      = (const float*)d_in[2];
    const float* c1i      = (const float*)d_in[3];
    const float* h2i      = (const float*)d_in[4];
    const float* c2i      = (const float*)d_in[5];
    const float* captions = (const float*)d_in[6];
    const float* W_ih1    = (const float*)d_in[7];
    const float* W_hh1    = (const float*)d_in[8];
    const float* b_ih1    = (const float*)d_in[9];
    const float* b_hh1    = (const float*)d_in[10];
    const float* W_ih2    = (const float*)d_in[11];
    const float* W_hh2    = (const float*)d_in[12];
    const float* b_ih2    = (const float*)d_in[13];
    const float* b_hh2    = (const float*)d_in[14];
    const float* W_att    = (const float*)d_in[15];
    // d_in[16] = b_att: unused (softmax shift-invariance)
    const float* W_comb   = (const float*)d_in[17];
    const float* b_comb   = (const float*)d_in[18];
    float* out = (float*)d_out;

    float *h1base, *h2base, *c1, *c2, *o, *q, *at;
    cudaGetSymbolAddress((void**)&h1base, g_h1);
    cudaGetSymbolAddress((void**)&h2base, g_h2);
    cudaGetSymbolAddress((void**)&c1, g_c1);
    cudaGetSymbolAddress((void**)&c2, g_c2);
    cudaGetSymbolAddress((void**)&o,  g_o);
    cudaGetSymbolAddress((void**)&q,  g_q);
    cudaGetSymbolAddress((void**)&at, g_at);

    float* h1p[2] = { h1base, h1base + Bsz * Hsz };
    float* h2p[2] = { h2base, h2base + Bsz * Hsz };

    const size_t SB = (size_t)Bsz * Hsz * sizeof(float);
    cudaMemcpyAsync(h1p[0], h1i, SB, cudaMemcpyDeviceToDevice, 0);
    cudaMemcpyAsync(c1,     c1i, SB, cudaMemcpyDeviceToDevice, 0);
    cudaMemcpyAsync(h2p[0], h2i, SB, cudaMemcpyDeviceToDevice, 0);
    cudaMemcpyAsync(c2,     c2i, SB, cudaMemcpyDeviceToDevice, 0);
    cudaMemsetAsync(o, 0, SB, 0);

    int cur = 0;
    for (int t = 0; t < Tsz; t++) {
        int nxt = cur ^ 1;
        // LSTM cell 1: x = captions[t] (B,E); segments (x,W_ih1) + (h1, W_hh1)
        lstm_kernel<2><<<128, 128>>>(
            captions + (size_t)t * Bsz * Esz, W_ih1, Esz, Esz,
            h1p[cur], W_hh1, Hsz, Hsz,
            nullptr, nullptr, 0, 0,
            b_ih1, b_hh1, h1p[nxt], c1);
        // LSTM cell 2: bar = [h1_new, o_prev]; segments split W_ih2 columns
        lstm_kernel<3><<<128, 128>>>(
            h1p[nxt], W_ih2, Hsz, 2 * Hsz,
            o, W_ih2 + Hsz, Hsz, 2 * Hsz,
            h2p[cur], W_hh2, Hsz, Hsz,
            b_ih2, b_hh2, h2p[nxt], c2);
        // q = h2_new @ W_att
        q_kernel<<<64, 128>>>(h2p[nxt], W_att, q);
        // attention -> a_t
        att_kernel<<<64, 256>>>(q, enc, masks, at);
        // o_t = tanh([a_t, h2] @ W_comb^T + b_comb) -> g_o and output slice
        comb_kernel<<<64, 128>>>(at, W_comb, h2p[nxt], W_comb + Hsz, b_comb,
                                 o, out + (size_t)t * Bsz * Hsz);
        cur = nxt;
    }
}

// round 3
// speedup vs baseline: 1.5897x; 1.5897x over previous
#include <cuda_runtime.h>
#include <math.h>

#define Bsz 64
#define Lsz 128
#define Tsz 48
#define Esz 512
#define HEsz 1024
#define Hsz 1024

// ---------------- scratch (device globals; no allocation allowed) ----------------
__device__ float g_h1[2][Bsz * Hsz];
__device__ float g_h2[2][Bsz * Hsz];
__device__ float g_c1[Bsz * Hsz];
__device__ float g_c2[Bsz * Hsz];
__device__ float g_o[Bsz * Hsz];
__device__ float g_q[Bsz * HEsz];
__device__ float g_at[Bsz * HEsz];
__device__ float g_e[Bsz * Lsz];

__device__ __forceinline__ float sigmoidf_(float x) { return 1.f / (1.f + expf(-x)); }

// =====================================================================
// LSTM cell: gates = sum_seg x_seg @ W_seg^T (+biases), then pointwise.
// CTA = 256 threads, ALL cooperate on each 32-k tile. Classic
// double-buffered smem pipeline with two __syncthreads per tile.
// Tile: 8 h x 4 gates (32 n) x 64 b. Grid = H/8 = 128.
// Thread owns (h = h0 + (tid&7), b = (tid>>3)*2 + {0,1}) -> acc[2][4].
// =====================================================================
template <int NSEG>
__global__ void __launch_bounds__(256) lstm_kernel(
    const float* __restrict__ x0, const float* __restrict__ w0, int K0, int ld0,
    const float* __restrict__ x1, const float* __restrict__ w1, int K1, int ld1,
    const float* __restrict__ x2, const float* __restrict__ w2, int K2, int ld2,
    const float* __restrict__ b_ih, const float* __restrict__ b_hh,
    float* __restrict__ h_out, float* __restrict__ c_io)
{
    __shared__ __align__(16) float Xs[2][32][68];  // [buf][k][b]
    __shared__ __align__(16) float Ws[2][32][36];  // [buf][k][n], n = hl*4+gate

    const int tid = threadIdx.x;   // 0..255
    const int tn = tid & 7;        // h within tile
    const int tb = tid >> 3;       // 0..31, 2 b each
    const int h0 = blockIdx.x * 8;

    const int tA = K0 >> 5;
    const int tB = tA + (K1 >> 5);
    const int nT = (NSEG > 2) ? (tB + (K2 >> 5)) : tB;

    float acc[2][4];
#pragma unroll
    for (int j = 0; j < 2; j++)
#pragma unroll
        for (int i = 0; i < 4; i++) acc[j][i] = 0.f;

    float4 xr[2], wr;

    auto load_tile = [&](int t) {
        const float* x; const float* w; int Ks, ldw, kt;
        if (t < tA)                   { x = x0; w = w0; Ks = K0; ldw = ld0; kt = t << 5; }
        else if (NSEG == 2 || t < tB) { x = x1; w = w1; Ks = K1; ldw = ld1; kt = (t - tA) << 5; }
        else                          { x = x2; w = w2; Ks = K2; ldw = ld2; kt = (t - tB) << 5; }
#pragma unroll
        for (int i = 0; i < 2; i++) {
            int idx = tid + (i << 8);          // 0..511
            int b = idx >> 3, k4 = idx & 7;
            xr[i] = *reinterpret_cast<const float4*>(x + b * Ks + kt + (k4 << 2));
        }
        {
            int n = tid >> 3, k4 = tid & 7;    // n 0..31
            int gate = n & 3, hl = n >> 2;
            wr = *reinterpret_cast<const float4*>(w + (size_t)(gate * Hsz + h0 + hl) * ldw + kt + (k4 << 2));
        }
    };

    auto stage = [&](int buf) {
#pragma unroll
        for (int i = 0; i < 2; i++) {
            int idx = tid + (i << 8);
            int b = idx >> 3, k4 = idx & 7;
            Xs[buf][k4 * 4 + 0][b] = xr[i].x;
            Xs[buf][k4 * 4 + 1][b] = xr[i].y;
            Xs[buf][k4 * 4 + 2][b] = xr[i].z;
            Xs[buf][k4 * 4 + 3][b] = xr[i].w;
        }
        {
            int n = tid >> 3, k4 = tid & 7;
            Ws[buf][k4 * 4 + 0][n] = wr.x;
            Ws[buf][k4 * 4 + 1][n] = wr.y;
            Ws[buf][k4 * 4 + 2][n] = wr.z;
            Ws[buf][k4 * 4 + 3][n] = wr.w;
        }
    };

    load_tile(0);
    stage(0);
    __syncthreads();

    for (int t = 0; t < nT; t++) {
        const int cb = t & 1;
        if (t + 1 < nT) load_tile(t + 1);   // LDG overlaps the FFMA burst
#pragma unroll
        for (int kk = 0; kk < 32; kk++) {
            float2 xv = *reinterpret_cast<const float2*>(&Xs[cb][kk][tb * 2]);
            float4 wv = *reinterpret_cast<const float4*>(&Ws[cb][kk][tn * 4]);
            acc[0][0] += xv.x * wv.x; acc[0][1] += xv.x * wv.y;
            acc[0][2] += xv.x * wv.z; acc[0][3] += xv.x * wv.w;
            acc[1][0] += xv.y * wv.x; acc[1][1] += xv.y * wv.y;
            acc[1][2] += xv.y * wv.z; acc[1][3] += xv.y * wv.w;
        }
        if (t + 1 < nT) {
            __syncthreads();       // everyone done reading buf cb^1's old data
            stage(cb ^ 1);
            __syncthreads();       // new tile visible
        }
    }

    const int h = h0 + tn;
    const float bi = b_ih[h] + b_hh[h];
    const float bf = b_ih[Hsz + h] + b_hh[Hsz + h];
    const float bg = b_ih[2 * Hsz + h] + b_hh[2 * Hsz + h];
    const float bo = b_ih[3 * Hsz + h] + b_hh[3 * Hsz + h];
#pragma unroll
    for (int j = 0; j < 2; j++) {
        int b = tb * 2 + j;
        float ig = sigmoidf_(acc[j][0] + bi);
        float fg = sigmoidf_(acc[j][1] + bf);
        float gg = tanhf(acc[j][2] + bg);
        float og = sigmoidf_(acc[j][3] + bo);
        float c = c_io[b * Hsz + h];
        float cn = fg * c + ig * gg;
        c_io[b * Hsz + h] = cn;
        h_out[b * Hsz + h] = og * tanhf(cn);
    }
}

// =====================================================================
// Small GEMM: C[64, 1024] = sum_seg X_seg @ Wop(W_seg). Tile 8 n / CTA,
// grid 128, 128 threads. Same two-sync double-buffer pipeline; each
// thread owns (b = tid>>1, n = n0 + (tid&1)*4 + i) with full-K acc[4].
// WT=0: w[n*ldw + k] (x @ W^T). WT=1: w[k*ldw + n] (x @ W).
// TANH=1: v = tanh(acc + bias[n]) written to out0 AND out1.
// =====================================================================
template <int NSEG, int TANH, int WT>
__global__ void __launch_bounds__(128) gemm8_kernel(
    const float* __restrict__ x0, const float* __restrict__ w0, int K0, int ld0,
    const float* __restrict__ x1, const float* __restrict__ w1, int K1, int ld1,
    const float* __restrict__ bias,
    float* __restrict__ out0, float* __restrict__ out1)
{
    __shared__ __align__(16) float Xs[2][32][68];
    __shared__ __align__(16) float Ws[2][32][12];

    const int tid = threadIdx.x;   // 0..127
    const int tn = tid & 1;
    const int tb = tid >> 1;       // one b per thread
    const int n0 = blockIdx.x * 8;

    const int tA = K0 >> 5;
    const int nT = (NSEG > 1) ? (tA + (K1 >> 5)) : tA;

    float acc[4] = {0.f, 0.f, 0.f, 0.f};

    float4 xr[4], wr;

    auto load_tile = [&](int t) {
        const float* x; const float* wp; int Ks, ldw, kt;
        if (NSEG == 1 || t < tA) { x = x0; wp = w0; Ks = K0; ldw = ld0; kt = t << 5; }
        else                     { x = x1; wp = w1; Ks = K1; ldw = ld1; kt = (t - tA) << 5; }
#pragma unroll
        for (int i = 0; i < 4; i++) {
            int idx = tid + (i << 7);          // 0..511
            int b = idx >> 3, k4 = idx & 7;
            xr[i] = *reinterpret_cast<const float4*>(x + b * Ks + kt + (k4 << 2));
        }
        if (tid < 64) {
            if (WT == 0) {
                int n = tid >> 3, k4 = tid & 7;
                wr = *reinterpret_cast<const float4*>(wp + (size_t)(n0 + n) * ldw + kt + (k4 << 2));
            } else {
                int kk = tid >> 1, n4 = tid & 1;
                wr = *reinterpret_cast<const float4*>(wp + (size_t)(kt + kk) * ldw + n0 + (n4 << 2));
            }
        }
    };

    auto stage = [&](int buf) {
#pragma unroll
        for (int i = 0; i < 4; i++) {
            int idx = tid + (i << 7);
            int b = idx >> 3, k4 = idx & 7;
            Xs[buf][k4 * 4 + 0][b] = xr[i].x;
            Xs[buf][k4 * 4 + 1][b] = xr[i].y;
            Xs[buf][k4 * 4 + 2][b] = xr[i].z;
            Xs[buf][k4 * 4 + 3][b] = xr[i].w;
        }
        if (tid < 64) {
            if (WT == 0) {
                int n = tid >> 3, k4 = tid & 7;
                Ws[buf][k4 * 4 + 0][n] = wr.x;
                Ws[buf][k4 * 4 + 1][n] = wr.y;
                Ws[buf][k4 * 4 + 2][n] = wr.z;
                Ws[buf][k4 * 4 + 3][n] = wr.w;
            } else {
                int kk = tid >> 1, n4 = tid & 1;
                Ws[buf][kk][n4 * 4 + 0] = wr.x;
                Ws[buf][kk][n4 * 4 + 1] = wr.y;
                Ws[buf][kk][n4 * 4 + 2] = wr.z;
                Ws[buf][kk][n4 * 4 + 3] = wr.w;
            }
        }
    };

    load_tile(0);
    stage(0);
    __syncthreads();

    for (int t = 0; t < nT; t++) {
        const int cb = t & 1;
        if (t + 1 < nT) load_tile(t + 1);
#pragma unroll
        for (int kk = 0; kk < 32; kk++) {
            float xv = Xs[cb][kk][tb];
            float4 wv = *reinterpret_cast<const float4*>(&Ws[cb][kk][tn * 4]);
            acc[0] += xv * wv.x;
            acc[1] += xv * wv.y;
            acc[2] += xv * wv.z;
            acc[3] += xv * wv.w;
        }
        if (t + 1 < nT) {
            __syncthreads();
            stage(cb ^ 1);
            __syncthreads();
        }
    }

    const int b = tb;
#pragma unroll
    for (int i = 0; i < 4; i++) {
        int n = n0 + tn * 4 + i;
        float v = acc[i];
        if (TANH) {
            v = tanhf(v + bias[n]);
            out0[b * 1024 + n] = v;
            out1[b * 1024 + n] = v;
        } else {
            out0[b * 1024 + n] = v;
        }
    }
}

// =====================================================================
// e[b,l] = q[b] . enc[b,l].  grid (4 l-chunks, 64 b), 256 threads.
// Each warp computes 4 l's via lane-strided float4 dot + shuffle reduce.
// =====================================================================
__global__ void __launch_bounds__(256) att_e_kernel(
    const float* __restrict__ q, const float* __restrict__ enc, float* __restrict__ e)
{
    const int b = blockIdx.y;
    const int lc = blockIdx.x;
    const int tid = threadIdx.x, lane = tid & 31, warp = tid >> 5;
    __shared__ __align__(16) float qs[HEsz];

#pragma unroll
    for (int i = 0; i < 4; i++) qs[tid + 256 * i] = q[b * HEsz + tid + 256 * i];
    __syncthreads();

    const float4* qs4 = reinterpret_cast<const float4*>(qs);
#pragma unroll
    for (int i = 0; i < 4; i++) {
        int l = lc * 32 + warp * 4 + i;
        const float4* er = reinterpret_cast<const float4*>(enc + (size_t)b * Lsz * HEsz + (size_t)l * HEsz);
        float s = 0.f;
#pragma unroll
        for (int jj = 0; jj < 8; jj++) {
            float4 a = qs4[lane + jj * 32];
            float4 c = er[lane + jj * 32];
            s += a.x * c.x + a.y * c.y + a.z * c.z + a.w * c.w;
        }
#pragma unroll
        for (int off = 16; off; off >>= 1) s += __shfl_xor_sync(0xffffffffu, s, off);
        if (lane == 0) e[b * Lsz + l] = s;
    }
}

// =====================================================================
// a_t[b,f] = sum_l softmax(masked e)[l] * enc[b,l,f].
// grid (4 f-chunks, 64 b), 256 threads; CTA recomputes the tiny softmax,
// then each thread accumulates one f over 128 l's.
// =====================================================================
__global__ void __launch_bounds__(256) att_av_kernel(
    const float* __restrict__ e, const int* __restrict__ masks,
    const float* __restrict__ enc, float* __restrict__ a_t)
{
    const int b = blockIdx.y;
    const int fc = blockIdx.x;
    const int tid = threadIdx.x;
    __shared__ float ev[Lsz];
    __shared__ float alpha[Lsz];

    if (tid < Lsz) {
        float v = e[b * Lsz + tid];
        ev[tid] = (masks[b * Lsz + tid] != 0) ? -INFINITY : v;
    }
    __syncthreads();
    if (tid < 32) {
        float v[4];
        float m = -INFINITY;
#pragma unroll
        for (int i = 0; i < 4; i++) { v[i] = ev[tid + 32 * i]; m = fmaxf(m, v[i]); }
#pragma unroll
        for (int off = 16; off; off >>= 1) m = fmaxf(m, __shfl_xor_sync(0xffffffffu, m, off));
        float s = 0.f;
#pragma unroll
        for (int i = 0; i < 4; i++) { v[i] = expf(v[i] - m); s += v[i]; }
#pragma unroll
        for (int off = 16; off; off >>= 1) s += __shfl_xor_sync(0xffffffffu, s, off);
        float inv = 1.f / s;
#pragma unroll
        for (int i = 0; i < 4; i++) alpha[tid + 32 * i] = v[i] * inv;
    }
    __syncthreads();

    const int f = fc * 256 + tid;
    const float* eb = enc + (size_t)b * Lsz * HEsz + f;
    float acc = 0.f;
#pragma unroll 4
    for (int l = 0; l < Lsz; l++) acc += alpha[l] * eb[(size_t)l * HEsz];
    a_t[b * HEsz + f] = acc;
}

// =====================================================================
extern "C" void kernel_launch(void* const* d_in, const int* in_sizes, int n_in,
                              void* d_out, int out_size)
{
    const float* enc      = (const float*)d_in[0];
    const int*   masks    = (const int*)d_in[1];
    const float* h1i      = (const float*)d_in[2];
    const float* c1i      = (const float*)d_in[3];
    const float* h2i      = (const float*)d_in[4];
    const float* c2i      = (const float*)d_in[5];
    const float* captions = (const float*)d_in[6];
    const float* W_ih1    = (const float*)d_in[7];
    const float* W_hh1    = (const float*)d_in[8];
    const float* b_ih1    = (const float*)d_in[9];
    const float* b_hh1    = (const float*)d_in[10];
    const float* W_ih2    = (const float*)d_in[11];
    const float* W_hh2    = (const float*)d_in[12];
    const float* b_ih2    = (const float*)d_in[13];
    const float* b_hh2    = (const float*)d_in[14];
    const float* W_att    = (const float*)d_in[15];
    // d_in[16] = b_att: unused (adds per-row constant; softmax shift-invariant)
    const float* W_comb   = (const float*)d_in[17];
    const float* b_comb   = (const float*)d_in[18];
    float* out = (float*)d_out;

    float *h1base, *h2base, *c1, *c2, *o, *q, *at, *e;
    cudaGetSymbolAddress((void**)&h1base, g_h1);
    cudaGetSymbolAddress((void**)&h2base, g_h2);
    cudaGetSymbolAddress((void**)&c1, g_c1);
    cudaGetSymbolAddress((void**)&c2, g_c2);
    cudaGetSymbolAddress((void**)&o,  g_o);
    cudaGetSymbolAddress((void**)&q,  g_q);
    cudaGetSymbolAddress((void**)&at, g_at);
    cudaGetSymbolAddress((void**)&e,  g_e);

    float* h1p[2] = { h1base, h1base + Bsz * Hsz };
    float* h2p[2] = { h2base, h2base + Bsz * Hsz };

    const size_t SB = (size_t)Bsz * Hsz * sizeof(float);
    cudaMemcpyAsync(h1p[0], h1i, SB, cudaMemcpyDeviceToDevice, 0);
    cudaMemcpyAsync(c1,     c1i, SB, cudaMemcpyDeviceToDevice, 0);
    cudaMemcpyAsync(h2p[0], h2i, SB, cudaMemcpyDeviceToDevice, 0);
    cudaMemcpyAsync(c2,     c2i, SB, cudaMemcpyDeviceToDevice, 0);
    cudaMemsetAsync(o, 0, SB, 0);

    int cur = 0;
    for (int t = 0; t < Tsz; t++) {
        int nxt = cur ^ 1;
        // LSTM cell 1: gates = captions[t] @ W_ih1^T + h1 @ W_hh1^T
        lstm_kernel<2><<<128, 256>>>(
            captions + (size_t)t * Bsz * Esz, W_ih1, Esz, Esz,
            h1p[cur], W_hh1, Hsz, Hsz,
            nullptr, nullptr, 0, 0,
            b_ih1, b_hh1, h1p[nxt], c1);
        // LSTM cell 2: bar = [h1_new, o_prev] via column-split of W_ih2
        lstm_kernel<3><<<128, 256>>>(
            h1p[nxt], W_ih2, Hsz, 2 * Hsz,
            o, W_ih2 + Hsz, Hsz, 2 * Hsz,
            h2p[cur], W_hh2, Hsz, Hsz,
            b_ih2, b_hh2, h2p[nxt], c2);
        // q = h2_new @ W_att  (W accessed transposed)
        gemm8_kernel<1, 0, 1><<<128, 128>>>(
            h2p[nxt], W_att, Hsz, HEsz,
            nullptr, nullptr, 0, 0,
            nullptr, q, nullptr);
        // e = q . enc
        att_e_kernel<<<dim3(4, 64), 256>>>(q, enc, e);
        // softmax + weighted sum -> a_t
        att_av_kernel<<<dim3(4, 64), 256>>>(e, masks, enc, at);
        // o_t = tanh([a_t, h2] @ W_comb^T + b_comb)
        gemm8_kernel<2, 1, 0><<<128, 128>>>(
            at, W_comb, Hsz, 2 * Hsz,
            h2p[nxt], W_comb + Hsz, Hsz, 2 * Hsz,
            b_comb, o, out + (size_t)t * Bsz * Hsz);
        cur = nxt;
    }
}